// round 11
// baseline (speedup 1.0000x reference)
#include <cuda_runtime.h>
#include <cuda_bf16.h>
#include <cstdint>

// ---------------------------------------------------------------------------
// BodyTransformer: mma.sync bf16-pair GEMMs. sm_103-safe (no tcgen05).
// qkv/ffn1: 128x128 tiles, 3-stage K16 cp.async, 2 CTAs/SM.
// wo/ffn2: 128x256 tiles with fused residual+LN epilogue.
// D = Ah*Bh + Ah*Bl + Al*Bh, fp32 register accumulation.
// ---------------------------------------------------------------------------

#define MM 131072

__device__ __align__(16) __nv_bfloat16 g_h_hi[(size_t)MM * 256];
__device__ __align__(16) __nv_bfloat16 g_h_lo[(size_t)MM * 256];
__device__ __align__(16) float         g_qkv[(size_t)MM * 768];
__device__ __align__(16) __nv_bfloat16 g_o_hi[(size_t)MM * 256];
__device__ __align__(16) __nv_bfloat16 g_o_lo[(size_t)MM * 256];
__device__ __align__(16) __nv_bfloat16 g_u_hi[(size_t)MM * 1024];
__device__ __align__(16) __nv_bfloat16 g_u_lo[(size_t)MM * 1024];
__device__ __align__(16) __nv_bfloat16 g_Bqkv_h[768 * 256], g_Bqkv_l[768 * 256];
__device__ __align__(16) __nv_bfloat16 g_Bo_h[256 * 256],   g_Bo_l[256 * 256];
__device__ __align__(16) __nv_bfloat16 g_B1_h[1024 * 256],  g_B1_l[1024 * 256];
__device__ __align__(16) __nv_bfloat16 g_B2_h[256 * 1024],  g_B2_l[256 * 1024];

static __device__ __forceinline__ uint32_t smem_u32(const void* p) {
    uint32_t a;
    asm("{ .reg .u64 t; cvta.to.shared.u64 t, %1; cvt.u32.u64 %0, t; }"
        : "=r"(a) : "l"(p));
    return a;
}
static __device__ __forceinline__ void ldm4(uint32_t* r, uint32_t addr) {
    asm volatile("ldmatrix.sync.aligned.m8n8.x4.shared.b16 {%0,%1,%2,%3}, [%4];"
                 : "=r"(r[0]), "=r"(r[1]), "=r"(r[2]), "=r"(r[3]) : "r"(addr));
}
static __device__ __forceinline__ void mma_bf16(float* d, const uint32_t* a,
                                                uint32_t b0, uint32_t b1) {
    asm volatile(
        "mma.sync.aligned.m16n8k16.row.col.f32.bf16.bf16.f32 "
        "{%0,%1,%2,%3}, {%4,%5,%6,%7}, {%8,%9}, {%0,%1,%2,%3};"
        : "+f"(d[0]), "+f"(d[1]), "+f"(d[2]), "+f"(d[3])
        : "r"(a[0]), "r"(a[1]), "r"(a[2]), "r"(a[3]), "r"(b0), "r"(b1));
}
static __device__ __forceinline__ void cpasync16(uint32_t sa, const void* g) {
    asm volatile("cp.async.cg.shared.global [%0], [%1], 16;"
                 :: "r"(sa), "l"(g) : "memory");
}
static __device__ __forceinline__ void cp_commit() {
    asm volatile("cp.async.commit_group;" ::: "memory");
}
static __device__ __forceinline__ void cp_wait1() {
    asm volatile("cp.async.wait_group 1;" ::: "memory");
}
static __device__ __forceinline__ void split_pair(float v, __nv_bfloat16& h,
                                                  __nv_bfloat16& l) {
    h = __float2bfloat16(v);
    l = __float2bfloat16(v - __bfloat162float(h));
}

// ===========================================================================
// gemm128: 128x128 tile, 256 threads, 3-stage K-chunk-16 pipeline,
// single barrier per stage. Row stride 24 bf16 (48B): granules (3r+c)%8
// distinct over 8 rows -> conflict-free ldmatrix.
// Stage layout (bytes): Ah@0 | Al@6144 | Bh@12288 | Bl@18432 ; stage=24576
// MODE 0: fp32 out (+bias); MODE 1: relu(+bias) -> bf16 pair.
// ===========================================================================
#define STG128 24576
template <int MODE>
static __device__ __forceinline__ void gemm128(
    const __nv_bfloat16* __restrict__ Ah, const __nv_bfloat16* __restrict__ Al,
    const __nv_bfloat16* __restrict__ Bh, const __nv_bfloat16* __restrict__ Bl,
    const float* __restrict__ bias, int K, int out_ld,
    float* __restrict__ outF,
    __nv_bfloat16* __restrict__ outPh, __nv_bfloat16* __restrict__ outPl) {
    extern __shared__ char sm[];
    const int tid = threadIdx.x;
    const int wid = tid >> 5;
    const int lane = tid & 31;
    const int wm = wid >> 2;       // 0..1 (64 rows)
    const int wn = wid & 3;        // 0..3 (32 cols)
    const int n0 = blockIdx.x * 128;
    const int m0 = blockIdx.y * 128;

    const __nv_bfloat16* __restrict__ gA0 = Ah + (size_t)m0 * K;
    const __nv_bfloat16* __restrict__ gA1 = Al + (size_t)m0 * K;
    const __nv_bfloat16* __restrict__ gB0 = Bh + (size_t)n0 * K;
    const __nv_bfloat16* __restrict__ gB1 = Bl + (size_t)n0 * K;
    const uint32_t smBase = smem_u32(sm);

    float acc[4][4][4];
#pragma unroll
    for (int mt = 0; mt < 4; ++mt)
#pragma unroll
        for (int nt = 0; nt < 4; ++nt)
#pragma unroll
            for (int e = 0; e < 4; ++e) acc[mt][nt][e] = 0.f;

    const int nst = K >> 4;

    auto load_stage = [&](int s) {
        const uint32_t sb = smBase + (uint32_t)((s % 3) * STG128);
        const int kc = s * 16;
#pragma unroll
        for (int i = 0; i < 4; ++i) {
            const int idx = tid + i * 256;       // 0..1023
            const int a4 = idx >> 8;             // 0=Ah 1=Al 2=Bh 3=Bl
            const int r = (idx & 255) >> 1;
            const int c = idx & 1;
            const uint32_t sa = sb + (uint32_t)(a4 * 6144 + r * 48 + c * 16);
            const __nv_bfloat16* g =
                (a4 == 0 ? gA0 : a4 == 1 ? gA1 : a4 == 2 ? gB0 : gB1);
            cpasync16(sa, g + (size_t)r * K + kc + c * 8);
        }
        cp_commit();
    };

    load_stage(0);
    load_stage(1);

    const uint32_t aOff = (uint32_t)((wm * 64 + (lane & 15)) * 48 + ((lane >> 4) << 4));
    const uint32_t bOff = (uint32_t)((wn * 32 + (lane & 15)) * 48 + ((lane >> 4) << 4));

    for (int s = 0; s < nst; ++s) {
        cp_wait1();
        __syncthreads();
        if (s + 2 < nst) load_stage(s + 2);
        else cp_commit();
        const uint32_t sb = smBase + (uint32_t)((s % 3) * STG128);
        const uint32_t aB = sb + aOff;
        const uint32_t alB = aB + 6144;
        const uint32_t bB = sb + 12288 + bOff;
        const uint32_t blB = bB + 6144;

        uint32_t bh[2][4], bl[2][4];
        ldm4(bh[0], bB);
        ldm4(bh[1], bB + 16 * 48);
        ldm4(bl[0], blB);
        ldm4(bl[1], blB + 16 * 48);
#pragma unroll
        for (int mt = 0; mt < 4; ++mt) {
            uint32_t ah[4], al[4];
            ldm4(ah, aB + (uint32_t)(mt * 16 * 48));
            ldm4(al, alB + (uint32_t)(mt * 16 * 48));
#pragma unroll
            for (int nt = 0; nt < 4; ++nt) {
                const int np = nt >> 1, sel = nt & 1;
                const uint32_t h0 = bh[np][sel], h1 = bh[np][sel + 2];
                const uint32_t l0 = bl[np][sel], l1 = bl[np][sel + 2];
                mma_bf16(acc[mt][nt], ah, h0, h1);
                mma_bf16(acc[mt][nt], ah, l0, l1);
                mma_bf16(acc[mt][nt], al, h0, h1);
            }
        }
    }

    const int r0 = lane >> 2;
    const int c0 = (lane & 3) * 2;
#pragma unroll
    for (int mt = 0; mt < 4; ++mt)
#pragma unroll
        for (int nt = 0; nt < 4; ++nt) {
            const int gc = n0 + wn * 32 + nt * 8 + c0;
            const float bx = bias[gc], by = bias[gc + 1];
#pragma unroll
            for (int half = 0; half < 2; ++half) {
                const int gr = m0 + wm * 64 + mt * 16 + r0 + half * 8;
                float vx = acc[mt][nt][2 * half] + bx;
                float vy = acc[mt][nt][2 * half + 1] + by;
                const size_t ro = (size_t)gr * out_ld + gc;
                if (MODE == 0) {
                    *(float2*)(outF + ro) = make_float2(vx, vy);
                } else {
                    vx = fmaxf(vx, 0.f); vy = fmaxf(vy, 0.f);
                    __nv_bfloat16 h0, h1, l0, l1;
                    split_pair(vx, h0, l0); split_pair(vy, h1, l1);
                    *(uint32_t*)(outPh + ro) =
                        (uint32_t)__bfloat16_as_ushort(h0) |
                        ((uint32_t)__bfloat16_as_ushort(h1) << 16);
                    *(uint32_t*)(outPl + ro) =
                        (uint32_t)__bfloat16_as_ushort(l0) |
                        ((uint32_t)__bfloat16_as_ushort(l1) << 16);
                }
            }
        }
}

// ===========================================================================
// gemm256: 128x256 tile, 512 threads, 3-stage K-chunk-32 (row stride 40),
// residual add + fused row-LN epilogue -> bf16 pair. (MODE 2 only)
// ===========================================================================
#define STAGE_B 61440
static __device__ __forceinline__ void gemm256_ln(
    const __nv_bfloat16* __restrict__ Ah, const __nv_bfloat16* __restrict__ Al,
    const __nv_bfloat16* __restrict__ Bh, const __nv_bfloat16* __restrict__ Bl,
    const float* __restrict__ bias, int K,
    float* __restrict__ resid,
    const float* __restrict__ lng, const float* __restrict__ lnb,
    __nv_bfloat16* __restrict__ outHh, __nv_bfloat16* __restrict__ outHl,
    int do_ln) {
    extern __shared__ char sm[];
    const int tid = threadIdx.x;
    const int wid = tid >> 5;
    const int lane = tid & 31;
    const int wm = wid >> 3;       // 0..1
    const int wn = wid & 7;        // 0..7
    const int m0 = blockIdx.y * 128;

    const __nv_bfloat16* __restrict__ gA0 = Ah + (size_t)m0 * K;
    const __nv_bfloat16* __restrict__ gA1 = Al + (size_t)m0 * K;
    const __nv_bfloat16* __restrict__ gB0 = Bh;
    const __nv_bfloat16* __restrict__ gB1 = Bl;
    const uint32_t smBase = smem_u32(sm);

    float acc[4][4][4];
#pragma unroll
    for (int mt = 0; mt < 4; ++mt)
#pragma unroll
        for (int nt = 0; nt < 4; ++nt)
#pragma unroll
            for (int e = 0; e < 4; ++e) acc[mt][nt][e] = 0.f;

    const int nst = K >> 5;

    auto load_stage = [&](int s) {
        const uint32_t sb = smBase + (uint32_t)((s % 3) * STAGE_B);
        const int kc = s * 32;
#pragma unroll
        for (int i = 0; i < 6; ++i) {
            const int idx = tid + i * 512;
            if (idx < 1024) {
                const int a2 = idx >> 9;
                const int r = (idx & 511) >> 2;
                const int c = idx & 3;
                const uint32_t sa = sb + (uint32_t)(a2 * 10240 + r * 80 + c * 16);
                const __nv_bfloat16* g = (a2 == 0 ? gA0 : gA1);
                cpasync16(sa, g + (size_t)r * K + kc + c * 8);
            } else {
                const int j = idx - 1024;
                const int a2 = j >> 10;
                const int r = (j & 1023) >> 2;
                const int c = j & 3;
                const uint32_t sa = sb + (uint32_t)(20480 + a2 * 20480 + r * 80 + c * 16);
                const __nv_bfloat16* g = (a2 == 0 ? gB0 : gB1);
                cpasync16(sa, g + (size_t)r * K + kc + c * 8);
            }
        }
        cp_commit();
    };

    load_stage(0);
    load_stage(1);

    const uint32_t aOff = (uint32_t)((wm * 64 + (lane & 15)) * 80 + ((lane >> 4) << 4));
    const uint32_t bOff = (uint32_t)((wn * 32 + (lane & 15)) * 80 + ((lane >> 4) << 4));

    for (int s = 0; s < nst; ++s) {
        cp_wait1();
        __syncthreads();
        if (s + 2 < nst) load_stage(s + 2);
        else cp_commit();
        const uint32_t sb = smBase + (uint32_t)((s % 3) * STAGE_B);
        const uint32_t aB = sb + aOff;
        const uint32_t alB = aB + 10240;
        const uint32_t bB = sb + 20480 + bOff;
        const uint32_t blB = bB + 20480;
#pragma unroll
        for (int st = 0; st < 2; ++st) {
            const uint32_t koff = (uint32_t)(st * 32);
            uint32_t bh[2][4], bl[2][4];
            ldm4(bh[0], bB + koff);
            ldm4(bh[1], bB + koff + 16 * 80);
            ldm4(bl[0], blB + koff);
            ldm4(bl[1], blB + koff + 16 * 80);
#pragma unroll
            for (int mt = 0; mt < 4; ++mt) {
                uint32_t ah[4], al[4];
                ldm4(ah, aB + koff + (uint32_t)(mt * 16 * 80));
                ldm4(al, alB + koff + (uint32_t)(mt * 16 * 80));
#pragma unroll
                for (int nt = 0; nt < 4; ++nt) {
                    const int np = nt >> 1, sel = nt & 1;
                    const uint32_t h0 = bh[np][sel], h1 = bh[np][sel + 2];
                    const uint32_t l0 = bl[np][sel], l1 = bl[np][sel + 2];
                    mma_bf16(acc[mt][nt], ah, h0, h1);
                    mma_bf16(acc[mt][nt], ah, l0, l1);
                    mma_bf16(acc[mt][nt], al, h0, h1);
                }
            }
        }
    }
    __syncthreads();

    const int r0 = lane >> 2;
    const int c0 = (lane & 3) * 2;

    float* red_s = (float*)sm;          // [128][8]
    float* red_q = red_s + 1024;        // [128][8]
    float* statm = red_q + 1024;        // [128]
    float* statr = statm + 128;         // [128]

    float rs[4][2], rq[4][2];
#pragma unroll
    for (int mt = 0; mt < 4; ++mt) { rs[mt][0] = rs[mt][1] = 0.f; rq[mt][0] = rq[mt][1] = 0.f; }

#pragma unroll
    for (int mt = 0; mt < 4; ++mt)
#pragma unroll
        for (int nt = 0; nt < 4; ++nt) {
            const int gc = wn * 32 + nt * 8 + c0;
            const float bx = bias[gc], by = bias[gc + 1];
#pragma unroll
            for (int half = 0; half < 2; ++half) {
                const int gr = m0 + wm * 64 + mt * 16 + r0 + half * 8;
                const size_t ro = (size_t)gr * 256 + gc;
                float2 xv = *(float2*)(resid + ro);
                float vx = acc[mt][nt][2 * half] + bx + xv.x;
                float vy = acc[mt][nt][2 * half + 1] + by + xv.y;
                *(float2*)(resid + ro) = make_float2(vx, vy);
                acc[mt][nt][2 * half] = vx;
                acc[mt][nt][2 * half + 1] = vy;
                rs[mt][half] += vx + vy;
                rq[mt][half] += vx * vx + vy * vy;
            }
        }
    if (do_ln) {
#pragma unroll
        for (int mt = 0; mt < 4; ++mt)
#pragma unroll
            for (int half = 0; half < 2; ++half) {
                float s = rs[mt][half], q = rq[mt][half];
                s += __shfl_xor_sync(0xffffffffu, s, 1);
                s += __shfl_xor_sync(0xffffffffu, s, 2);
                q += __shfl_xor_sync(0xffffffffu, q, 1);
                q += __shfl_xor_sync(0xffffffffu, q, 2);
                if ((lane & 3) == 0) {
                    const int lr = wm * 64 + mt * 16 + r0 + half * 8;
                    red_s[lr * 8 + wn] = s;
                    red_q[lr * 8 + wn] = q;
                }
            }
        __syncthreads();
        if (tid < 128) {
            float s = 0.f, q = 0.f;
#pragma unroll
            for (int w = 0; w < 8; ++w) { s += red_s[tid * 8 + w]; q += red_q[tid * 8 + w]; }
            const float mean = s * 0.00390625f;
            const float var = q * 0.00390625f - mean * mean;
            statm[tid] = mean;
            statr[tid] = rsqrtf(var + 1e-5f);
        }
        __syncthreads();
#pragma unroll
        for (int mt = 0; mt < 4; ++mt)
#pragma unroll
            for (int nt = 0; nt < 4; ++nt) {
                const int gc = wn * 32 + nt * 8 + c0;
                const float gx = lng[gc], gy = lng[gc + 1];
                const float tx = lnb[gc], ty = lnb[gc + 1];
#pragma unroll
                for (int half = 0; half < 2; ++half) {
                    const int lr = wm * 64 + mt * 16 + r0 + half * 8;
                    const float mean = statm[lr], rstd = statr[lr];
                    const float hx = (acc[mt][nt][2 * half] - mean) * rstd * gx + tx;
                    const float hy = (acc[mt][nt][2 * half + 1] - mean) * rstd * gy + ty;
                    __nv_bfloat16 h0, h1, l0, l1;
                    split_pair(hx, h0, l0); split_pair(hy, h1, l1);
                    const size_t ro = (size_t)(m0 + lr) * 256 + gc;
                    *(uint32_t*)(outHh + ro) =
                        (uint32_t)__bfloat16_as_ushort(h0) |
                        ((uint32_t)__bfloat16_as_ushort(h1) << 16);
                    *(uint32_t*)(outHl + ro) =
                        (uint32_t)__bfloat16_as_ushort(l0) |
                        ((uint32_t)__bfloat16_as_ushort(l1) << 16);
                }
            }
    }
}

__global__ void __launch_bounds__(256)
k_gemm_qkv(const float* __restrict__ bias) {
    gemm128<0>(g_h_hi, g_h_lo, g_Bqkv_h, g_Bqkv_l, bias, 256, 768,
               g_qkv, nullptr, nullptr);
}
__global__ void __launch_bounds__(256)
k_gemm_ffn1(const float* __restrict__ bias) {
    gemm128<1>(g_h_hi, g_h_lo, g_B1_h, g_B1_l, bias, 256, 1024,
               nullptr, g_u_hi, g_u_lo);
}
__global__ void __launch_bounds__(512)
k_gemm_wo_ln(const float* __restrict__ bias, float* __restrict__ x,
             const float* __restrict__ lng, const float* __restrict__ lnb) {
    gemm256_ln(g_o_hi, g_o_lo, g_Bo_h, g_Bo_l, bias, 256, x, lng, lnb,
               g_h_hi, g_h_lo, 1);
}
__global__ void __launch_bounds__(512)
k_gemm_ffn2_ln(const float* __restrict__ bias, float* __restrict__ x,
               const float* __restrict__ lng, const float* __restrict__ lnb,
               int do_ln) {
    gemm256_ln(g_u_hi, g_u_lo, g_B2_h, g_B2_l, bias, 1024, x, lng, lnb,
               g_h_hi, g_h_lo, do_ln);
}

// ---------------- initial LayerNorm: x -> bf16 pair --------------------------
__global__ void __launch_bounds__(256)
k_ln(const float* __restrict__ x, const float* __restrict__ g,
     const float* __restrict__ bta) {
    const int row = blockIdx.x * 8 + (threadIdx.x >> 5);
    const int lane = threadIdx.x & 31;
    const float* rp = x + (size_t)row * 256 + lane * 8;
    const float4 a = *(const float4*)rp;
    const float4 b4 = *(const float4*)(rp + 4);
    float vals[8] = {a.x, a.y, a.z, a.w, b4.x, b4.y, b4.z, b4.w};
    float s = 0.f, s2 = 0.f;
#pragma unroll
    for (int j = 0; j < 8; ++j) { s += vals[j]; s2 = fmaf(vals[j], vals[j], s2); }
#pragma unroll
    for (int off = 16; off; off >>= 1) {
        s += __shfl_xor_sync(0xffffffffu, s, off);
        s2 += __shfl_xor_sync(0xffffffffu, s2, off);
    }
    const float mean = s * 0.00390625f;
    const float var = s2 * 0.00390625f - mean * mean;
    const float rstd = rsqrtf(var + 1e-5f);
    uint32_t phv[4], plv[4];
#pragma unroll
    for (int j = 0; j < 4; ++j) {
        const int c0 = lane * 8 + 2 * j;
        float v0 = (vals[2 * j] - mean) * rstd * g[c0] + bta[c0];
        float v1 = (vals[2 * j + 1] - mean) * rstd * g[c0 + 1] + bta[c0 + 1];
        __nv_bfloat16 h0, h1, l0, l1;
        split_pair(v0, h0, l0); split_pair(v1, h1, l1);
        phv[j] = (uint32_t)__bfloat16_as_ushort(h0) |
                 ((uint32_t)__bfloat16_as_ushort(h1) << 16);
        plv[j] = (uint32_t)__bfloat16_as_ushort(l0) |
                 ((uint32_t)__bfloat16_as_ushort(l1) << 16);
    }
    const size_t o = (size_t)row * 256 + lane * 8;
    *(uint4*)(g_h_hi + o) = make_uint4(phv[0], phv[1], phv[2], phv[3]);
    *(uint4*)(g_h_lo + o) = make_uint4(plv[0], plv[1], plv[2], plv[3]);
}

// ---------------- Attention (fp32, banded |i-j|<=1) --------------------------
__global__ void __launch_bounds__(256, 2)
k_attn() {
    extern __shared__ float smf[];  // [32][776]
    const int b = blockIdx.x;
    const int tid = threadIdx.x;
    const int wid = tid >> 5;
    const int lane = tid & 31;
    const float* gq = g_qkv + (size_t)b * 24576;
    for (int r = wid; r < 32; r += 8)
#pragma unroll
        for (int j = 0; j < 24; ++j)
            smf[r * 776 + j * 32 + lane] = gq[r * 768 + j * 32 + lane];
    __syncthreads();

    const int h = wid;
    float kreg[32];
#pragma unroll
    for (int d = 0; d < 32; ++d)
        kreg[d] = smf[lane * 776 + 256 + h * 32 + d];
    const float SC = 0.17677669529663689f;
    for (int i = 0; i < 32; ++i) {
        const float* qrow = smf + i * 776 + h * 32;
        float s = 0.f;
#pragma unroll
        for (int d = 0; d < 32; ++d) s = fmaf(qrow[d], kreg[d], s);
        s *= SC;
        int dj = lane - i;
        if (dj < 0) dj = -dj;
        if (dj > 1) s -= 1e9f;
        float m = s;
#pragma unroll
        for (int off = 16; off; off >>= 1)
            m = fmaxf(m, __shfl_xor_sync(0xffffffffu, m, off));
        const float e = expf(s - m);
        float sum = e;
#pragma unroll
        for (int off = 16; off; off >>= 1)
            sum += __shfl_xor_sync(0xffffffffu, sum, off);
        const float w = e / sum;
        float o = 0.f;
        const int j0 = (i > 0) ? i - 1 : 0;
        const int j1 = (i < 31) ? i + 1 : 31;
        for (int j = j0; j <= j1; ++j) {
            const float wj = __shfl_sync(0xffffffffu, w, j);
            o = fmaf(wj, smf[j * 776 + 512 + h * 32 + lane], o);
        }
        const size_t ro = (size_t)(b * 32 + i) * 256 + h * 32 + lane;
        __nv_bfloat16 hh, ll;
        split_pair(o, hh, ll);
        g_o_hi[ro] = hh;
        g_o_lo[ro] = ll;
    }
}

// ---------------- merged weight prep ----------------------------------------
__global__ void k_split_all(const float* __restrict__ wqkv,
                            const float* __restrict__ wo,
                            const float* __restrict__ w1,
                            const float* __restrict__ w2) {
    int i = blockIdx.x * 256 + threadIdx.x;
    if (i < 196608) {
        split_pair(wqkv[i], g_Bqkv_h[i], g_Bqkv_l[i]);
    } else if (i < 262144) {
        int j = i - 196608;
        split_pair(wo[j], g_Bo_h[j], g_Bo_l[j]);
    } else if (i < 524288) {
        int j = i - 262144;
        int f = j >> 8, k = j & 255;
        split_pair(w1[k * 1024 + f], g_B1_h[j], g_B1_l[j]);
    } else if (i < 786432) {
        int j = i - 524288;
        int c = j >> 10, k = j & 1023;
        split_pair(w2[k * 256 + c], g_B2_h[j], g_B2_l[j]);
    }
}

// ---------------- Tokenizer (fp32, proven) -----------------------------------
__global__ void __launch_bounds__(256)
bt_tokenize(const float* __restrict__ obs, const float* __restrict__ embW,
            const float* __restrict__ embB, const float* __restrict__ pos,
            float* __restrict__ out) {
    __shared__ float obs_s[32 * 128];
    const int n = blockIdx.x;
    const int b0 = blockIdx.y * 32;
    const int tid = threadIdx.x;
    const float* src = obs + b0 * 128;
    for (int i = tid; i < 4096; i += 256) obs_s[i] = src[i];
    __syncthreads();
    const int e = tid;
    float acc[32];
#pragma unroll
    for (int bb = 0; bb < 32; ++bb) acc[bb] = 0.f;
    const float* wb = embW + n * 32768 + e;
    for (int d0 = 0; d0 < 128; d0 += 16) {
        float w[16];
#pragma unroll
        for (int dd = 0; dd < 16; ++dd) w[dd] = wb[(d0 + dd) * 256];
#pragma unroll
        for (int bb = 0; bb < 32; ++bb) {
            const float4* orow = (const float4*)(obs_s + bb * 128 + d0);
            float4 o0 = orow[0], o1 = orow[1], o2 = orow[2], o3 = orow[3];
            float a = acc[bb];
            a = fmaf(o0.x, w[0], a);  a = fmaf(o0.y, w[1], a);
            a = fmaf(o0.z, w[2], a);  a = fmaf(o0.w, w[3], a);
            a = fmaf(o1.x, w[4], a);  a = fmaf(o1.y, w[5], a);
            a = fmaf(o1.z, w[6], a);  a = fmaf(o1.w, w[7], a);
            a = fmaf(o2.x, w[8], a);  a = fmaf(o2.y, w[9], a);
            a = fmaf(o2.z, w[10], a); a = fmaf(o2.w, w[11], a);
            a = fmaf(o3.x, w[12], a); a = fmaf(o3.y, w[13], a);
            a = fmaf(o3.z, w[14], a); a = fmaf(o3.w, w[15], a);
            acc[bb] = a;
        }
    }
    const float add = embB[n * 256 + e] + pos[n * 256 + e];
#pragma unroll
    for (int bb = 0; bb < 32; ++bb)
        out[(b0 + bb) * 8192 + n * 256 + e] = acc[bb] + add;
}

extern "C" void kernel_launch(void* const* d_in, const int* in_sizes, int n_in,
                              void* d_out, int out_size) {
    (void)in_sizes; (void)n_in; (void)out_size;
    const float* obs  = (const float*)d_in[0];
    const float* embW = (const float*)d_in[1];
    const float* embB = (const float*)d_in[2];
    const float* pos  = (const float*)d_in[3];
    const float* Wqkv = (const float*)d_in[4];
    const float* bqkv = (const float*)d_in[5];
    const float* Wo   = (const float*)d_in[6];
    const float* bo   = (const float*)d_in[7];
    const float* ln1g = (const float*)d_in[8];
    const float* ln1b = (const float*)d_in[9];
    const float* ln2g = (const float*)d_in[10];
    const float* ln2b = (const float*)d_in[11];
    const float* W1   = (const float*)d_in[12];
    const float* b1   = (const float*)d_in[13];
    const float* W2   = (const float*)d_in[14];
    const float* b2   = (const float*)d_in[15];
    float* x = (float*)d_out;

    const int G128 = 3 * STG128;        // 73728
    const int G256 = 3 * STAGE_B;       // 184320
    const int ASMEM = 32 * 776 * 4;     // 99328
    cudaFuncSetAttribute(k_gemm_qkv,     cudaFuncAttributeMaxDynamicSharedMemorySize, G128);
    cudaFuncSetAttribute(k_gemm_ffn1,    cudaFuncAttributeMaxDynamicSharedMemorySize, G128);
    cudaFuncSetAttribute(k_gemm_wo_ln,   cudaFuncAttributeMaxDynamicSharedMemorySize, G256);
    cudaFuncSetAttribute(k_gemm_ffn2_ln, cudaFuncAttributeMaxDynamicSharedMemorySize, G256);
    cudaFuncSetAttribute(k_attn,         cudaFuncAttributeMaxDynamicSharedMemorySize, ASMEM);

    k_split_all<<<3072, 256>>>(Wqkv, Wo, W1, W2);
    bt_tokenize<<<dim3(32, 128), 256>>>(obs, embW, embB, pos, x);
    k_ln<<<16384, 256>>>(x, ln1g, ln1b);

    for (int l = 0; l < 6; ++l) {
        k_gemm_qkv<<<dim3(6, 1024), 256, G128>>>(bqkv);
        k_attn<<<4096, 256, ASMEM>>>();
        k_gemm_wo_ln<<<dim3(1, 1024), 512, G256>>>(bo, x, ln2g, ln2b);
        k_gemm_ffn1<<<dim3(8, 1024), 256, G128>>>(b1);
        k_gemm_ffn2_ln<<<dim3(1, 1024), 512, G256>>>(b2, x, ln1g, ln1b,
                                                     (l < 5) ? 1 : 0);
    }
}

// round 12
// speedup vs baseline: 1.0791x; 1.0791x over previous
#include <cuda_runtime.h>
#include <cuda_bf16.h>
#include <cstdint>

// ---------------------------------------------------------------------------
// BodyTransformer via mma.sync bf16-pair GEMMs + cp.async pipeline (sm_103)
// R9 config (128x128, K32, 2-stage) + MMA pass-reordering (break RAW chains).
// D = Ah*Bh + Ah*Bl + Al*Bh, fp32 register accumulation.
// ---------------------------------------------------------------------------

#define MM 131072

__device__ __align__(16) __nv_bfloat16 g_h_hi[(size_t)MM * 256];
__device__ __align__(16) __nv_bfloat16 g_h_lo[(size_t)MM * 256];
__device__ __align__(16) float         g_qkv[(size_t)MM * 768];
__device__ __align__(16) __nv_bfloat16 g_o_hi[(size_t)MM * 256];
__device__ __align__(16) __nv_bfloat16 g_o_lo[(size_t)MM * 256];
__device__ __align__(16) __nv_bfloat16 g_u_hi[(size_t)MM * 1024];
__device__ __align__(16) __nv_bfloat16 g_u_lo[(size_t)MM * 1024];
__device__ __align__(16) __nv_bfloat16 g_Bqkv_h[768 * 256], g_Bqkv_l[768 * 256];
__device__ __align__(16) __nv_bfloat16 g_Bo_h[256 * 256],   g_Bo_l[256 * 256];
__device__ __align__(16) __nv_bfloat16 g_B1_h[1024 * 256],  g_B1_l[1024 * 256];
__device__ __align__(16) __nv_bfloat16 g_B2_h[256 * 1024],  g_B2_l[256 * 1024];

static __device__ __forceinline__ uint32_t smem_u32(const void* p) {
    uint32_t a;
    asm("{ .reg .u64 t; cvta.to.shared.u64 t, %1; cvt.u32.u64 %0, t; }"
        : "=r"(a) : "l"(p));
    return a;
}
static __device__ __forceinline__ void ldm4(uint32_t* r, uint32_t addr) {
    asm volatile("ldmatrix.sync.aligned.m8n8.x4.shared.b16 {%0,%1,%2,%3}, [%4];"
                 : "=r"(r[0]), "=r"(r[1]), "=r"(r[2]), "=r"(r[3]) : "r"(addr));
}
static __device__ __forceinline__ void mma_bf16(float* d, const uint32_t* a,
                                                uint32_t b0, uint32_t b1) {
    asm volatile(
        "mma.sync.aligned.m16n8k16.row.col.f32.bf16.bf16.f32 "
        "{%0,%1,%2,%3}, {%4,%5,%6,%7}, {%8,%9}, {%0,%1,%2,%3};"
        : "+f"(d[0]), "+f"(d[1]), "+f"(d[2]), "+f"(d[3])
        : "r"(a[0]), "r"(a[1]), "r"(a[2]), "r"(a[3]), "r"(b0), "r"(b1));
}
static __device__ __forceinline__ void cpasync16(uint32_t sa, const void* g) {
    asm volatile("cp.async.cg.shared.global [%0], [%1], 16;"
                 :: "r"(sa), "l"(g) : "memory");
}
static __device__ __forceinline__ void cp_commit() {
    asm volatile("cp.async.commit_group;" ::: "memory");
}
static __device__ __forceinline__ void cp_wait1() {
    asm volatile("cp.async.wait_group 1;" ::: "memory");
}
static __device__ __forceinline__ void split_pair(float v, __nv_bfloat16& h,
                                                  __nv_bfloat16& l) {
    h = __float2bfloat16(v);
    l = __float2bfloat16(v - __bfloat162float(h));
}

// ---------------------------------------------------------------------------
// Pipelined GEMM: D[128x128] = A_pair[m0..,K] * B_pair[n0..,K]^T (+ epilogue)
// 2-stage cp.async double buffer, K-chunk 32. Row stride 40 bf16 (80 B).
// MODE 0: fp32 +bias; 1: relu+bias -> bf16 pair; 2: resid += (+bias)
// smem: 2 stages x 4 arrays x 128x40 bf16 = 81920 B
// ---------------------------------------------------------------------------
#define RW 40            // bf16 per row
#define ARR 5120         // elems per array (128*40)
#define STAGE (4 * ARR)  // elems per stage

template <int MODE>
static __device__ __forceinline__ void gemm_body(
    const __nv_bfloat16* __restrict__ Ah, const __nv_bfloat16* __restrict__ Al,
    const __nv_bfloat16* __restrict__ Bh, const __nv_bfloat16* __restrict__ Bl,
    const float* __restrict__ bias, float* __restrict__ outF,
    __nv_bfloat16* __restrict__ outPh, __nv_bfloat16* __restrict__ outPl,
    float* __restrict__ resid, int K, int out_ld) {
    extern __shared__ __nv_bfloat16 sm[];

    const int tid = threadIdx.x;
    const int wid = tid >> 5;
    const int lane = tid & 31;
    const int wm = wid >> 2;       // 0..1
    const int wn = wid & 3;        // 0..3
    const int n0 = blockIdx.x * 128;
    const int m0 = blockIdx.y * 128;

    const __nv_bfloat16* gbase[4] = {Ah + (size_t)m0 * K, Al + (size_t)m0 * K,
                                     Bh + (size_t)n0 * K, Bl + (size_t)n0 * K};
    const uint32_t smBase = smem_u32(sm);

    float acc[4][4][4];
#pragma unroll
    for (int mt = 0; mt < 4; ++mt)
#pragma unroll
        for (int nt = 0; nt < 4; ++nt)
#pragma unroll
            for (int e = 0; e < 4; ++e) acc[mt][nt][e] = 0.f;

    const int nst = K >> 5;

    auto load_stage = [&](int s, int kc) {
        const uint32_t sb = smBase + (uint32_t)((s & 1) * STAGE * 2);
#pragma unroll
        for (int i = 0; i < 8; ++i) {
            const int idx = tid + i * 256;
            const int a2 = idx >> 9;
            const int r = (idx >> 2) & 127;
            const int c = idx & 3;
            const uint32_t sa = sb + (uint32_t)(a2 * ARR * 2 + r * RW * 2 + c * 16);
            cpasync16(sa, gbase[a2] + (size_t)r * K + kc * 32 + c * 8);
        }
        cp_commit();
    };

    load_stage(0, 0);
    if (nst > 1) load_stage(1, 1); else cp_commit();

    const uint32_t aOff = (uint32_t)((wm * 64 + (lane & 15)) * RW * 2 + ((lane >> 4) << 4));
    const uint32_t bOff = (uint32_t)((wn * 32 + (lane & 15)) * RW * 2 + ((lane >> 4) << 4));

    for (int s = 0; s < nst; ++s) {
        cp_wait1();
        __syncthreads();
        const uint32_t sb = smBase + (uint32_t)((s & 1) * STAGE * 2);
        const uint32_t aB = sb + aOff;
        const uint32_t alB = aB + ARR * 2;
        const uint32_t bB = sb + 2u * ARR * 2 + bOff;
        const uint32_t blB = bB + ARR * 2;
#pragma unroll
        for (int st = 0; st < 2; ++st) {
            const uint32_t koff = (uint32_t)(st * 32);
            uint32_t bh[2][4], bl[2][4];
            ldm4(bh[0], bB + koff);
            ldm4(bh[1], bB + koff + 16 * RW * 2);
            ldm4(bl[0], blB + koff);
            ldm4(bl[1], blB + koff + 16 * RW * 2);
#pragma unroll
            for (int mt = 0; mt < 4; ++mt) {
                uint32_t ah[4], al[4];
                ldm4(ah, aB + koff + (uint32_t)(mt * 16 * RW * 2));
                ldm4(al, alB + koff + (uint32_t)(mt * 16 * RW * 2));
                // pass-major ordering: consecutive MMAs hit different
                // accumulators (reuse distance 4 instead of 1).
#pragma unroll
                for (int nt = 0; nt < 4; ++nt) {
                    const int np = nt >> 1, sel = nt & 1;
                    mma_bf16(acc[mt][nt], ah, bh[np][sel], bh[np][sel + 2]);
                }
#pragma unroll
                for (int nt = 0; nt < 4; ++nt) {
                    const int np = nt >> 1, sel = nt & 1;
                    mma_bf16(acc[mt][nt], ah, bl[np][sel], bl[np][sel + 2]);
                }
#pragma unroll
                for (int nt = 0; nt < 4; ++nt) {
                    const int np = nt >> 1, sel = nt & 1;
                    mma_bf16(acc[mt][nt], al, bh[np][sel], bh[np][sel + 2]);
                }
            }
        }
        __syncthreads();
        if (s + 2 < nst) load_stage(s + 2, s + 2);
        else cp_commit();
    }

    const int r0 = lane >> 2;
    const int c0 = (lane & 3) * 2;
#pragma unroll
    for (int mt = 0; mt < 4; ++mt) {
#pragma unroll
        for (int nt = 0; nt < 4; ++nt) {
            const int gc = n0 + wn * 32 + nt * 8 + c0;
            const float bx = bias[gc], by = bias[gc + 1];
#pragma unroll
            for (int half = 0; half < 2; ++half) {
                const int gr = m0 + wm * 64 + mt * 16 + r0 + half * 8;
                float vx = acc[mt][nt][2 * half] + bx;
                float vy = acc[mt][nt][2 * half + 1] + by;
                const size_t ro = (size_t)gr * out_ld + gc;
                if (MODE == 0) {
                    *(float2*)(outF + ro) = make_float2(vx, vy);
                } else if (MODE == 2) {
                    float2 xv = *(float2*)(resid + ro);
                    xv.x += vx; xv.y += vy;
                    *(float2*)(resid + ro) = xv;
                } else {
                    vx = fmaxf(vx, 0.f); vy = fmaxf(vy, 0.f);
                    __nv_bfloat16 h0, h1, l0, l1;
                    split_pair(vx, h0, l0); split_pair(vy, h1, l1);
                    *(uint32_t*)(outPh + ro) =
                        (uint32_t)__bfloat16_as_ushort(h0) |
                        ((uint32_t)__bfloat16_as_ushort(h1) << 16);
                    *(uint32_t*)(outPl + ro) =
                        (uint32_t)__bfloat16_as_ushort(l0) |
                        ((uint32_t)__bfloat16_as_ushort(l1) << 16);
                }
            }
        }
    }
}

__global__ void __launch_bounds__(256, 2)
k_gemm_qkv(const float* __restrict__ bias) {
    gemm_body<0>(g_h_hi, g_h_lo, g_Bqkv_h, g_Bqkv_l, bias, g_qkv,
                 nullptr, nullptr, nullptr, 256, 768);
}
__global__ void __launch_bounds__(256, 2)
k_gemm_wo(const float* __restrict__ bias, float* __restrict__ x) {
    gemm_body<2>(g_o_hi, g_o_lo, g_Bo_h, g_Bo_l, bias, nullptr,
                 nullptr, nullptr, x, 256, 256);
}
__global__ void __launch_bounds__(256, 2)
k_gemm_ffn1(const float* __restrict__ bias) {
    gemm_body<1>(g_h_hi, g_h_lo, g_B1_h, g_B1_l, bias, nullptr,
                 g_u_hi, g_u_lo, nullptr, 256, 1024);
}
__global__ void __launch_bounds__(256, 2)
k_gemm_ffn2(const float* __restrict__ bias, float* __restrict__ x) {
    gemm_body<2>(g_u_hi, g_u_lo, g_B2_h, g_B2_l, bias, nullptr,
                 nullptr, nullptr, x, 1024, 256);
}

// ---------------- LayerNorm: x -> bf16 pair ---------------------------------
__global__ void __launch_bounds__(256)
k_ln(const float* __restrict__ x, const float* __restrict__ g,
     const float* __restrict__ bta) {
    const int row = blockIdx.x * 8 + (threadIdx.x >> 5);
    const int lane = threadIdx.x & 31;
    const float* rp = x + (size_t)row * 256 + lane * 8;
    const float4 a = *(const float4*)rp;
    const float4 b4 = *(const float4*)(rp + 4);
    float vals[8] = {a.x, a.y, a.z, a.w, b4.x, b4.y, b4.z, b4.w};
    float s = 0.f, s2 = 0.f;
#pragma unroll
    for (int j = 0; j < 8; ++j) { s += vals[j]; s2 = fmaf(vals[j], vals[j], s2); }
#pragma unroll
    for (int off = 16; off; off >>= 1) {
        s += __shfl_xor_sync(0xffffffffu, s, off);
        s2 += __shfl_xor_sync(0xffffffffu, s2, off);
    }
    const float mean = s * 0.00390625f;
    const float var = s2 * 0.00390625f - mean * mean;
    const float rstd = rsqrtf(var + 1e-5f);
    uint32_t phv[4], plv[4];
#pragma unroll
    for (int j = 0; j < 4; ++j) {
        const int c0 = lane * 8 + 2 * j;
        float v0 = (vals[2 * j] - mean) * rstd * g[c0] + bta[c0];
        float v1 = (vals[2 * j + 1] - mean) * rstd * g[c0 + 1] + bta[c0 + 1];
        __nv_bfloat16 h0, h1, l0, l1;
        split_pair(v0, h0, l0); split_pair(v1, h1, l1);
        phv[j] = (uint32_t)__bfloat16_as_ushort(h0) |
                 ((uint32_t)__bfloat16_as_ushort(h1) << 16);
        plv[j] = (uint32_t)__bfloat16_as_ushort(l0) |
                 ((uint32_t)__bfloat16_as_ushort(l1) << 16);
    }
    const size_t o = (size_t)row * 256 + lane * 8;
    *(uint4*)(g_h_hi + o) = make_uint4(phv[0], phv[1], phv[2], phv[3]);
    *(uint4*)(g_h_lo + o) = make_uint4(plv[0], plv[1], plv[2], plv[3]);
}

// ---------------- Attention (fp32, banded |i-j|<=1) --------------------------
__global__ void __launch_bounds__(256, 2)
k_attn() {
    extern __shared__ float smf[];  // [32][776]
    const int b = blockIdx.x;
    const int tid = threadIdx.x;
    const int wid = tid >> 5;
    const int lane = tid & 31;
    const float* gq = g_qkv + (size_t)b * 24576;
    for (int r = wid; r < 32; r += 8)
#pragma unroll
        for (int j = 0; j < 24; ++j)
            smf[r * 776 + j * 32 + lane] = gq[r * 768 + j * 32 + lane];
    __syncthreads();

    const int h = wid;
    float kreg[32];
#pragma unroll
    for (int d = 0; d < 32; ++d)
        kreg[d] = smf[lane * 776 + 256 + h * 32 + d];
    const float SC = 0.17677669529663689f;
    for (int i = 0; i < 32; ++i) {
        const float* qrow = smf + i * 776 + h * 32;
        float s = 0.f;
#pragma unroll
        for (int d = 0; d < 32; ++d) s = fmaf(qrow[d], kreg[d], s);
        s *= SC;
        int dj = lane - i;
        if (dj < 0) dj = -dj;
        if (dj > 1) s -= 1e9f;
        float m = s;
#pragma unroll
        for (int off = 16; off; off >>= 1)
            m = fmaxf(m, __shfl_xor_sync(0xffffffffu, m, off));
        const float e = expf(s - m);
        float sum = e;
#pragma unroll
        for (int off = 16; off; off >>= 1)
            sum += __shfl_xor_sync(0xffffffffu, sum, off);
        const float w = e / sum;
        float o = 0.f;
        const int j0 = (i > 0) ? i - 1 : 0;
        const int j1 = (i < 31) ? i + 1 : 31;
        for (int j = j0; j <= j1; ++j) {
            const float wj = __shfl_sync(0xffffffffu, w, j);
            o = fmaf(wj, smf[j * 776 + 512 + h * 32 + lane], o);
        }
        const size_t ro = (size_t)(b * 32 + i) * 256 + h * 32 + lane;
        __nv_bfloat16 hh, ll;
        split_pair(o, hh, ll);
        g_o_hi[ro] = hh;
        g_o_lo[ro] = ll;
    }
}

// ---------------- merged weight prep ----------------------------------------
__global__ void k_split_all(const float* __restrict__ wqkv,
                            const float* __restrict__ wo,
                            const float* __restrict__ w1,
                            const float* __restrict__ w2) {
    int i = blockIdx.x * 256 + threadIdx.x;
    if (i < 196608) {
        split_pair(wqkv[i], g_Bqkv_h[i], g_Bqkv_l[i]);
    } else if (i < 262144) {
        int j = i - 196608;
        split_pair(wo[j], g_Bo_h[j], g_Bo_l[j]);
    } else if (i < 524288) {
        int j = i - 262144;
        int f = j >> 8, k = j & 255;
        split_pair(w1[k * 1024 + f], g_B1_h[j], g_B1_l[j]);
    } else if (i < 786432) {
        int j = i - 524288;
        int c = j >> 10, k = j & 1023;
        split_pair(w2[k * 256 + c], g_B2_h[j], g_B2_l[j]);
    }
}

// ---------------- Tokenizer (fp32, proven) -----------------------------------
__global__ void __launch_bounds__(256)
bt_tokenize(const float* __restrict__ obs, const float* __restrict__ embW,
            const float* __restrict__ embB, const float* __restrict__ pos,
            float* __restrict__ out) {
    __shared__ float obs_s[32 * 128];
    const int n = blockIdx.x;
    const int b0 = blockIdx.y * 32;
    const int tid = threadIdx.x;
    const float* src = obs + b0 * 128;
    for (int i = tid; i < 4096; i += 256) obs_s[i] = src[i];
    __syncthreads();
    const int e = tid;
    float acc[32];
#pragma unroll
    for (int bb = 0; bb < 32; ++bb) acc[bb] = 0.f;
    const float* wb = embW + n * 32768 + e;
    for (int d0 = 0; d0 < 128; d0 += 16) {
        float w[16];
#pragma unroll
        for (int dd = 0; dd < 16; ++dd) w[dd] = wb[(d0 + dd) * 256];
#pragma unroll
        for (int bb = 0; bb < 32; ++bb) {
            const float4* orow = (const float4*)(obs_s + bb * 128 + d0);
            float4 o0 = orow[0], o1 = orow[1], o2 = orow[2], o3 = orow[3];
            float a = acc[bb];
            a = fmaf(o0.x, w[0], a);  a = fmaf(o0.y, w[1], a);
            a = fmaf(o0.z, w[2], a);  a = fmaf(o0.w, w[3], a);
            a = fmaf(o1.x, w[4], a);  a = fmaf(o1.y, w[5], a);
            a = fmaf(o1.z, w[6], a);  a = fmaf(o1.w, w[7], a);
            a = fmaf(o2.x, w[8], a);  a = fmaf(o2.y, w[9], a);
            a = fmaf(o2.z, w[10], a); a = fmaf(o2.w, w[11], a);
            a = fmaf(o3.x, w[12], a); a = fmaf(o3.y, w[13], a);
            a = fmaf(o3.z, w[14], a); a = fmaf(o3.w, w[15], a);
            acc[bb] = a;
        }
    }
    const float add = embB[n * 256 + e] + pos[n * 256 + e];
#pragma unroll
    for (int bb = 0; bb < 32; ++bb)
        out[(b0 + bb) * 8192 + n * 256 + e] = acc[bb] + add;
}

extern "C" void kernel_launch(void* const* d_in, const int* in_sizes, int n_in,
                              void* d_out, int out_size) {
    (void)in_sizes; (void)n_in; (void)out_size;
    const float* obs  = (const float*)d_in[0];
    const float* embW = (const float*)d_in[1];
    const float* embB = (const float*)d_in[2];
    const float* pos  = (const float*)d_in[3];
    const float* Wqkv = (const float*)d_in[4];
    const float* bqkv = (const float*)d_in[5];
    const float* Wo   = (const float*)d_in[6];
    const float* bo   = (const float*)d_in[7];
    const float* ln1g = (const float*)d_in[8];
    const float* ln1b = (const float*)d_in[9];
    const float* ln2g = (const float*)d_in[10];
    const float* ln2b = (const float*)d_in[11];
    const float* W1   = (const float*)d_in[12];
    const float* b1   = (const float*)d_in[13];
    const float* W2   = (const float*)d_in[14];
    const float* b2   = (const float*)d_in[15];
    float* x = (float*)d_out;

    const int GSMEM = 2 * STAGE * 2;  // 81920 B
    const int ASMEM = 32 * 776 * 4;   // 99328 B
    cudaFuncSetAttribute(k_gemm_qkv,  cudaFuncAttributeMaxDynamicSharedMemorySize, GSMEM);
    cudaFuncSetAttribute(k_gemm_wo,   cudaFuncAttributeMaxDynamicSharedMemorySize, GSMEM);
    cudaFuncSetAttribute(k_gemm_ffn1, cudaFuncAttributeMaxDynamicSharedMemorySize, GSMEM);
    cudaFuncSetAttribute(k_gemm_ffn2, cudaFuncAttributeMaxDynamicSharedMemorySize, GSMEM);
    cudaFuncSetAttribute(k_attn,      cudaFuncAttributeMaxDynamicSharedMemorySize, ASMEM);

    k_split_all<<<3072, 256>>>(Wqkv, Wo, W1, W2);
    bt_tokenize<<<dim3(32, 128), 256>>>(obs, embW, embB, pos, x);

    for (int l = 0; l < 6; ++l) {
        k_ln<<<16384, 256>>>(x, ln1g, ln1b);
        k_gemm_qkv<<<dim3(6, 1024), 256, GSMEM>>>(bqkv);
        k_attn<<<4096, 256, ASMEM>>>();
        k_gemm_wo<<<dim3(2, 1024), 256, GSMEM>>>(bo, x);
        k_ln<<<16384, 256>>>(x, ln2g, ln2b);
        k_gemm_ffn1<<<dim3(8, 1024), 256, GSMEM>>>(b1);
        k_gemm_ffn2<<<dim3(2, 1024), 256, GSMEM>>>(b2, x);
    }
}

// round 13
// speedup vs baseline: 1.0986x; 1.0180x over previous
#include <cuda_runtime.h>
#include <cuda_bf16.h>
#include <cstdint>

// ---------------------------------------------------------------------------
// BodyTransformer via mma.sync bf16-pair GEMMs + cp.async pipeline (sm_103)
// R12 + mt-pair interleave: 8-accumulator window, HMMA reuse distance 8.
// D = Ah*Bh + Ah*Bl + Al*Bh, fp32 register accumulation.
// ---------------------------------------------------------------------------

#define MM 131072

__device__ __align__(16) __nv_bfloat16 g_h_hi[(size_t)MM * 256];
__device__ __align__(16) __nv_bfloat16 g_h_lo[(size_t)MM * 256];
__device__ __align__(16) float         g_qkv[(size_t)MM * 768];
__device__ __align__(16) __nv_bfloat16 g_o_hi[(size_t)MM * 256];
__device__ __align__(16) __nv_bfloat16 g_o_lo[(size_t)MM * 256];
__device__ __align__(16) __nv_bfloat16 g_u_hi[(size_t)MM * 1024];
__device__ __align__(16) __nv_bfloat16 g_u_lo[(size_t)MM * 1024];
__device__ __align__(16) __nv_bfloat16 g_Bqkv_h[768 * 256], g_Bqkv_l[768 * 256];
__device__ __align__(16) __nv_bfloat16 g_Bo_h[256 * 256],   g_Bo_l[256 * 256];
__device__ __align__(16) __nv_bfloat16 g_B1_h[1024 * 256],  g_B1_l[1024 * 256];
__device__ __align__(16) __nv_bfloat16 g_B2_h[256 * 1024],  g_B2_l[256 * 1024];

static __device__ __forceinline__ uint32_t smem_u32(const void* p) {
    uint32_t a;
    asm("{ .reg .u64 t; cvta.to.shared.u64 t, %1; cvt.u32.u64 %0, t; }"
        : "=r"(a) : "l"(p));
    return a;
}
static __device__ __forceinline__ void ldm4(uint32_t* r, uint32_t addr) {
    asm volatile("ldmatrix.sync.aligned.m8n8.x4.shared.b16 {%0,%1,%2,%3}, [%4];"
                 : "=r"(r[0]), "=r"(r[1]), "=r"(r[2]), "=r"(r[3]) : "r"(addr));
}
static __device__ __forceinline__ void mma_bf16(float* d, const uint32_t* a,
                                                uint32_t b0, uint32_t b1) {
    asm volatile(
        "mma.sync.aligned.m16n8k16.row.col.f32.bf16.bf16.f32 "
        "{%0,%1,%2,%3}, {%4,%5,%6,%7}, {%8,%9}, {%0,%1,%2,%3};"
        : "+f"(d[0]), "+f"(d[1]), "+f"(d[2]), "+f"(d[3])
        : "r"(a[0]), "r"(a[1]), "r"(a[2]), "r"(a[3]), "r"(b0), "r"(b1));
}
static __device__ __forceinline__ void cpasync16(uint32_t sa, const void* g) {
    asm volatile("cp.async.cg.shared.global [%0], [%1], 16;"
                 :: "r"(sa), "l"(g) : "memory");
}
static __device__ __forceinline__ void cp_commit() {
    asm volatile("cp.async.commit_group;" ::: "memory");
}
static __device__ __forceinline__ void cp_wait1() {
    asm volatile("cp.async.wait_group 1;" ::: "memory");
}
static __device__ __forceinline__ void split_pair(float v, __nv_bfloat16& h,
                                                  __nv_bfloat16& l) {
    h = __float2bfloat16(v);
    l = __float2bfloat16(v - __bfloat162float(h));
}

// ---------------------------------------------------------------------------
// Pipelined GEMM: D[128x128] = A_pair[m0..,K] * B_pair[n0..,K]^T (+ epilogue)
// 2-stage cp.async double buffer, K-chunk 32. Row stride 40 bf16 (80 B).
// MODE 0: fp32 +bias; 1: relu+bias -> bf16 pair; 2: resid += (+bias)
// smem: 2 stages x 4 arrays x 128x40 bf16 = 81920 B
// ---------------------------------------------------------------------------
#define RW 40            // bf16 per row
#define ARR 5120         // elems per array (128*40)
#define STAGE (4 * ARR)  // elems per stage

template <int MODE>
static __device__ __forceinline__ void gemm_body(
    const __nv_bfloat16* __restrict__ Ah, const __nv_bfloat16* __restrict__ Al,
    const __nv_bfloat16* __restrict__ Bh, const __nv_bfloat16* __restrict__ Bl,
    const float* __restrict__ bias, float* __restrict__ outF,
    __nv_bfloat16* __restrict__ outPh, __nv_bfloat16* __restrict__ outPl,
    float* __restrict__ resid, int K, int out_ld) {
    extern __shared__ __nv_bfloat16 sm[];

    const int tid = threadIdx.x;
    const int wid = tid >> 5;
    const int lane = tid & 31;
    const int wm = wid >> 2;       // 0..1
    const int wn = wid & 3;        // 0..3
    const int n0 = blockIdx.x * 128;
    const int m0 = blockIdx.y * 128;

    const __nv_bfloat16* gbase[4] = {Ah + (size_t)m0 * K, Al + (size_t)m0 * K,
                                     Bh + (size_t)n0 * K, Bl + (size_t)n0 * K};
    const uint32_t smBase = smem_u32(sm);

    float acc[4][4][4];
#pragma unroll
    for (int mt = 0; mt < 4; ++mt)
#pragma unroll
        for (int nt = 0; nt < 4; ++nt)
#pragma unroll
            for (int e = 0; e < 4; ++e) acc[mt][nt][e] = 0.f;

    const int nst = K >> 5;

    auto load_stage = [&](int s, int kc) {
        const uint32_t sb = smBase + (uint32_t)((s & 1) * STAGE * 2);
#pragma unroll
        for (int i = 0; i < 8; ++i) {
            const int idx = tid + i * 256;
            const int a2 = idx >> 9;
            const int r = (idx >> 2) & 127;
            const int c = idx & 3;
            const uint32_t sa = sb + (uint32_t)(a2 * ARR * 2 + r * RW * 2 + c * 16);
            cpasync16(sa, gbase[a2] + (size_t)r * K + kc * 32 + c * 8);
        }
        cp_commit();
    };

    load_stage(0, 0);
    if (nst > 1) load_stage(1, 1); else cp_commit();

    const uint32_t aOff = (uint32_t)((wm * 64 + (lane & 15)) * RW * 2 + ((lane >> 4) << 4));
    const uint32_t bOff = (uint32_t)((wn * 32 + (lane & 15)) * RW * 2 + ((lane >> 4) << 4));

    for (int s = 0; s < nst; ++s) {
        cp_wait1();
        __syncthreads();
        const uint32_t sb = smBase + (uint32_t)((s & 1) * STAGE * 2);
        const uint32_t aB = sb + aOff;
        const uint32_t alB = aB + ARR * 2;
        const uint32_t bB = sb + 2u * ARR * 2 + bOff;
        const uint32_t blB = bB + ARR * 2;
#pragma unroll
        for (int st = 0; st < 2; ++st) {
            const uint32_t koff = (uint32_t)(st * 32);
            uint32_t bh[2][4], bl[2][4];
            ldm4(bh[0], bB + koff);
            ldm4(bh[1], bB + koff + 16 * RW * 2);
            ldm4(bl[0], blB + koff);
            ldm4(bl[1], blB + koff + 16 * RW * 2);
            // mt pairs: 8-accumulator window, reuse distance 8.
#pragma unroll
            for (int mp = 0; mp < 2; ++mp) {
                uint32_t ah[2][4], al[2][4];
                ldm4(ah[0], aB + koff + (uint32_t)((2 * mp) * 16 * RW * 2));
                ldm4(ah[1], aB + koff + (uint32_t)((2 * mp + 1) * 16 * RW * 2));
                ldm4(al[0], alB + koff + (uint32_t)((2 * mp) * 16 * RW * 2));
                ldm4(al[1], alB + koff + (uint32_t)((2 * mp + 1) * 16 * RW * 2));
#pragma unroll
                for (int q = 0; q < 2; ++q)
#pragma unroll
                    for (int nt = 0; nt < 4; ++nt) {
                        const int np = nt >> 1, sel = nt & 1;
                        mma_bf16(acc[2 * mp + q][nt], ah[q],
                                 bh[np][sel], bh[np][sel + 2]);
                    }
#pragma unroll
                for (int q = 0; q < 2; ++q)
#pragma unroll
                    for (int nt = 0; nt < 4; ++nt) {
                        const int np = nt >> 1, sel = nt & 1;
                        mma_bf16(acc[2 * mp + q][nt], ah[q],
                                 bl[np][sel], bl[np][sel + 2]);
                    }
#pragma unroll
                for (int q = 0; q < 2; ++q)
#pragma unroll
                    for (int nt = 0; nt < 4; ++nt) {
                        const int np = nt >> 1, sel = nt & 1;
                        mma_bf16(acc[2 * mp + q][nt], al[q],
                                 bh[np][sel], bh[np][sel + 2]);
                    }
            }
        }
        __syncthreads();
        if (s + 2 < nst) load_stage(s + 2, s + 2);
        else cp_commit();
    }

    const int r0 = lane >> 2;
    const int c0 = (lane & 3) * 2;
#pragma unroll
    for (int mt = 0; mt < 4; ++mt) {
#pragma unroll
        for (int nt = 0; nt < 4; ++nt) {
            const int gc = n0 + wn * 32 + nt * 8 + c0;
            const float bx = bias[gc], by = bias[gc + 1];
#pragma unroll
            for (int half = 0; half < 2; ++half) {
                const int gr = m0 + wm * 64 + mt * 16 + r0 + half * 8;
                float vx = acc[mt][nt][2 * half] + bx;
                float vy = acc[mt][nt][2 * half + 1] + by;
                const size_t ro = (size_t)gr * out_ld + gc;
                if (MODE == 0) {
                    *(float2*)(outF + ro) = make_float2(vx, vy);
                } else if (MODE == 2) {
                    float2 xv = *(float2*)(resid + ro);
                    xv.x += vx; xv.y += vy;
                    *(float2*)(resid + ro) = xv;
                } else {
                    vx = fmaxf(vx, 0.f); vy = fmaxf(vy, 0.f);
                    __nv_bfloat16 h0, h1, l0, l1;
                    split_pair(vx, h0, l0); split_pair(vy, h1, l1);
                    *(uint32_t*)(outPh + ro) =
                        (uint32_t)__bfloat16_as_ushort(h0) |
                        ((uint32_t)__bfloat16_as_ushort(h1) << 16);
                    *(uint32_t*)(outPl + ro) =
                        (uint32_t)__bfloat16_as_ushort(l0) |
                        ((uint32_t)__bfloat16_as_ushort(l1) << 16);
                }
            }
        }
    }
}

__global__ void __launch_bounds__(256, 2)
k_gemm_qkv(const float* __restrict__ bias) {
    gemm_body<0>(g_h_hi, g_h_lo, g_Bqkv_h, g_Bqkv_l, bias, g_qkv,
                 nullptr, nullptr, nullptr, 256, 768);
}
__global__ void __launch_bounds__(256, 2)
k_gemm_wo(const float* __restrict__ bias, float* __restrict__ x) {
    gemm_body<2>(g_o_hi, g_o_lo, g_Bo_h, g_Bo_l, bias, nullptr,
                 nullptr, nullptr, x, 256, 256);
}
__global__ void __launch_bounds__(256, 2)
k_gemm_ffn1(const float* __restrict__ bias) {
    gemm_body<1>(g_h_hi, g_h_lo, g_B1_h, g_B1_l, bias, nullptr,
                 g_u_hi, g_u_lo, nullptr, 256, 1024);
}
__global__ void __launch_bounds__(256, 2)
k_gemm_ffn2(const float* __restrict__ bias, float* __restrict__ x) {
    gemm_body<2>(g_u_hi, g_u_lo, g_B2_h, g_B2_l, bias, nullptr,
                 nullptr, nullptr, x, 1024, 256);
}

// ---------------- LayerNorm: x -> bf16 pair ---------------------------------
__global__ void __launch_bounds__(256)
k_ln(const float* __restrict__ x, const float* __restrict__ g,
     const float* __restrict__ bta) {
    const int row = blockIdx.x * 8 + (threadIdx.x >> 5);
    const int lane = threadIdx.x & 31;
    const float* rp = x + (size_t)row * 256 + lane * 8;
    const float4 a = *(const float4*)rp;
    const float4 b4 = *(const float4*)(rp + 4);
    float vals[8] = {a.x, a.y, a.z, a.w, b4.x, b4.y, b4.z, b4.w};
    float s = 0.f, s2 = 0.f;
#pragma unroll
    for (int j = 0; j < 8; ++j) { s += vals[j]; s2 = fmaf(vals[j], vals[j], s2); }
#pragma unroll
    for (int off = 16; off; off >>= 1) {
        s += __shfl_xor_sync(0xffffffffu, s, off);
        s2 += __shfl_xor_sync(0xffffffffu, s2, off);
    }
    const float mean = s * 0.00390625f;
    const float var = s2 * 0.00390625f - mean * mean;
    const float rstd = rsqrtf(var + 1e-5f);
    uint32_t phv[4], plv[4];
#pragma unroll
    for (int j = 0; j < 4; ++j) {
        const int c0 = lane * 8 + 2 * j;
        float v0 = (vals[2 * j] - mean) * rstd * g[c0] + bta[c0];
        float v1 = (vals[2 * j + 1] - mean) * rstd * g[c0 + 1] + bta[c0 + 1];
        __nv_bfloat16 h0, h1, l0, l1;
        split_pair(v0, h0, l0); split_pair(v1, h1, l1);
        phv[j] = (uint32_t)__bfloat16_as_ushort(h0) |
                 ((uint32_t)__bfloat16_as_ushort(h1) << 16);
        plv[j] = (uint32_t)__bfloat16_as_ushort(l0) |
                 ((uint32_t)__bfloat16_as_ushort(l1) << 16);
    }
    const size_t o = (size_t)row * 256 + lane * 8;
    *(uint4*)(g_h_hi + o) = make_uint4(phv[0], phv[1], phv[2], phv[3]);
    *(uint4*)(g_h_lo + o) = make_uint4(plv[0], plv[1], plv[2], plv[3]);
}

// ---------------- Attention (fp32, banded |i-j|<=1) --------------------------
__global__ void __launch_bounds__(256, 2)
k_attn() {
    extern __shared__ float smf[];  // [32][776]
    const int b = blockIdx.x;
    const int tid = threadIdx.x;
    const int wid = tid >> 5;
    const int lane = tid & 31;
    const float* gq = g_qkv + (size_t)b * 24576;
    for (int r = wid; r < 32; r += 8)
#pragma unroll
        for (int j = 0; j < 24; ++j)
            smf[r * 776 + j * 32 + lane] = gq[r * 768 + j * 32 + lane];
    __syncthreads();

    const int h = wid;
    float kreg[32];
#pragma unroll
    for (int d = 0; d < 32; ++d)
        kreg[d] = smf[lane * 776 + 256 + h * 32 + d];
    const float SC = 0.17677669529663689f;
    for (int i = 0; i < 32; ++i) {
        const float* qrow = smf + i * 776 + h * 32;
        float s = 0.f;
#pragma unroll
        for (int d = 0; d < 32; ++d) s = fmaf(qrow[d], kreg[d], s);
        s *= SC;
        int dj = lane - i;
        if (dj < 0) dj = -dj;
        if (dj > 1) s -= 1e9f;
        float m = s;
#pragma unroll
        for (int off = 16; off; off >>= 1)
            m = fmaxf(m, __shfl_xor_sync(0xffffffffu, m, off));
        const float e = expf(s - m);
        float sum = e;
#pragma unroll
        for (int off = 16; off; off >>= 1)
            sum += __shfl_xor_sync(0xffffffffu, sum, off);
        const float w = e / sum;
        float o = 0.f;
        const int j0 = (i > 0) ? i - 1 : 0;
        const int j1 = (i < 31) ? i + 1 : 31;
        for (int j = j0; j <= j1; ++j) {
            const float wj = __shfl_sync(0xffffffffu, w, j);
            o = fmaf(wj, smf[j * 776 + 512 + h * 32 + lane], o);
        }
        const size_t ro = (size_t)(b * 32 + i) * 256 + h * 32 + lane;
        __nv_bfloat16 hh, ll;
        split_pair(o, hh, ll);
        g_o_hi[ro] = hh;
        g_o_lo[ro] = ll;
    }
}

// ---------------- merged weight prep ----------------------------------------
__global__ void k_split_all(const float* __restrict__ wqkv,
                            const float* __restrict__ wo,
                            const float* __restrict__ w1,
                            const float* __restrict__ w2) {
    int i = blockIdx.x * 256 + threadIdx.x;
    if (i < 196608) {
        split_pair(wqkv[i], g_Bqkv_h[i], g_Bqkv_l[i]);
    } else if (i < 262144) {
        int j = i - 196608;
        split_pair(wo[j], g_Bo_h[j], g_Bo_l[j]);
    } else if (i < 524288) {
        int j = i - 262144;
        int f = j >> 8, k = j & 255;
        split_pair(w1[k * 1024 + f], g_B1_h[j], g_B1_l[j]);
    } else if (i < 786432) {
        int j = i - 524288;
        int c = j >> 10, k = j & 1023;
        split_pair(w2[k * 256 + c], g_B2_h[j], g_B2_l[j]);
    }
}

// ---------------- Tokenizer (fp32, proven) -----------------------------------
__global__ void __launch_bounds__(256)
bt_tokenize(const float* __restrict__ obs, const float* __restrict__ embW,
            const float* __restrict__ embB, const float* __restrict__ pos,
            float* __restrict__ out) {
    __shared__ float obs_s[32 * 128];
    const int n = blockIdx.x;
    const int b0 = blockIdx.y * 32;
    const int tid = threadIdx.x;
    const float* src = obs + b0 * 128;
    for (int i = tid; i < 4096; i += 256) obs_s[i] = src[i];
    __syncthreads();
    const int e = tid;
    float acc[32];
#pragma unroll
    for (int bb = 0; bb < 32; ++bb) acc[bb] = 0.f;
    const float* wb = embW + n * 32768 + e;
    for (int d0 = 0; d0 < 128; d0 += 16) {
        float w[16];
#pragma unroll
        for (int dd = 0; dd < 16; ++dd) w[dd] = wb[(d0 + dd) * 256];
#pragma unroll
        for (int bb = 0; bb < 32; ++bb) {
            const float4* orow = (const float4*)(obs_s + bb * 128 + d0);
            float4 o0 = orow[0], o1 = orow[1], o2 = orow[2], o3 = orow[3];
            float a = acc[bb];
            a = fmaf(o0.x, w[0], a);  a = fmaf(o0.y, w[1], a);
            a = fmaf(o0.z, w[2], a);  a = fmaf(o0.w, w[3], a);
            a = fmaf(o1.x, w[4], a);  a = fmaf(o1.y, w[5], a);
            a = fmaf(o1.z, w[6], a);  a = fmaf(o1.w, w[7], a);
            a = fmaf(o2.x, w[8], a);  a = fmaf(o2.y, w[9], a);
            a = fmaf(o2.z, w[10], a); a = fmaf(o2.w, w[11], a);
            a = fmaf(o3.x, w[12], a); a = fmaf(o3.y, w[13], a);
            a = fmaf(o3.z, w[14], a); a = fmaf(o3.w, w[15], a);
            acc[bb] = a;
        }
    }
    const float add = embB[n * 256 + e] + pos[n * 256 + e];
#pragma unroll
    for (int bb = 0; bb < 32; ++bb)
        out[(b0 + bb) * 8192 + n * 256 + e] = acc[bb] + add;
}

extern "C" void kernel_launch(void* const* d_in, const int* in_sizes, int n_in,
                              void* d_out, int out_size) {
    (void)in_sizes; (void)n_in; (void)out_size;
    const float* obs  = (const float*)d_in[0];
    const float* embW = (const float*)d_in[1];
    const float* embB = (const float*)d_in[2];
    const float* pos  = (const float*)d_in[3];
    const float* Wqkv = (const float*)d_in[4];
    const float* bqkv = (const float*)d_in[5];
    const float* Wo   = (const float*)d_in[6];
    const float* bo   = (const float*)d_in[7];
    const float* ln1g = (const float*)d_in[8];
    const float* ln1b = (const float*)d_in[9];
    const float* ln2g = (const float*)d_in[10];
    const float* ln2b = (const float*)d_in[11];
    const float* W1   = (const float*)d_in[12];
    const float* b1   = (const float*)d_in[13];
    const float* W2   = (const float*)d_in[14];
    const float* b2   = (const float*)d_in[15];
    float* x = (float*)d_out;

    const int GSMEM = 2 * STAGE * 2;  // 81920 B
    const int ASMEM = 32 * 776 * 4;   // 99328 B
    cudaFuncSetAttribute(k_gemm_qkv,  cudaFuncAttributeMaxDynamicSharedMemorySize, GSMEM);
    cudaFuncSetAttribute(k_gemm_wo,   cudaFuncAttributeMaxDynamicSharedMemorySize, GSMEM);
    cudaFuncSetAttribute(k_gemm_ffn1, cudaFuncAttributeMaxDynamicSharedMemorySize, GSMEM);
    cudaFuncSetAttribute(k_gemm_ffn2, cudaFuncAttributeMaxDynamicSharedMemorySize, GSMEM);
    cudaFuncSetAttribute(k_attn,      cudaFuncAttributeMaxDynamicSharedMemorySize, ASMEM);

    k_split_all<<<3072, 256>>>(Wqkv, Wo, W1, W2);
    bt_tokenize<<<dim3(32, 128), 256>>>(obs, embW, embB, pos, x);

    for (int l = 0; l < 6; ++l) {
        k_ln<<<16384, 256>>>(x, ln1g, ln1b);
        k_gemm_qkv<<<dim3(6, 1024), 256, GSMEM>>>(bqkv);
        k_attn<<<4096, 256, ASMEM>>>();
        k_gemm_wo<<<dim3(2, 1024), 256, GSMEM>>>(bo, x);
        k_ln<<<16384, 256>>>(x, ln2g, ln2b);
        k_gemm_ffn1<<<dim3(8, 1024), 256, GSMEM>>>(b1);
        k_gemm_ffn2<<<dim3(2, 1024), 256, GSMEM>>>(b2, x);
    }
}

// round 14
// speedup vs baseline: 2.0483x; 1.8645x over previous
#include <cuda_runtime.h>
#include <cuda_fp16.h>
#include <cstdint>

// ---------------------------------------------------------------------------
// BodyTransformer via single-pass fp16 mma.sync GEMMs + cp.async (sm_103)
// fp16 (11-bit mantissa) single product replaces bf16 hi/lo 3-pass:
// 3x less MMA work, 2x less activation traffic. fp32 accumulate.
// ---------------------------------------------------------------------------

#define MM 131072

__device__ __align__(16) __half g_h[(size_t)MM * 256];        // LN output
__device__ __align__(16) float  g_qkv[(size_t)MM * 768];
__device__ __align__(16) __half g_o[(size_t)MM * 256];        // attn output
__device__ __align__(16) __half g_u[(size_t)MM * 1024];       // ffn1 output
__device__ __align__(16) __half g_Bqkv[768 * 256];
__device__ __align__(16) __half g_Bo[256 * 256];
__device__ __align__(16) __half g_B1[1024 * 256];
__device__ __align__(16) __half g_B2[256 * 1024];

static __device__ __forceinline__ uint32_t smem_u32(const void* p) {
    uint32_t a;
    asm("{ .reg .u64 t; cvta.to.shared.u64 t, %1; cvt.u32.u64 %0, t; }"
        : "=r"(a) : "l"(p));
    return a;
}
static __device__ __forceinline__ void ldm4(uint32_t* r, uint32_t addr) {
    asm volatile("ldmatrix.sync.aligned.m8n8.x4.shared.b16 {%0,%1,%2,%3}, [%4];"
                 : "=r"(r[0]), "=r"(r[1]), "=r"(r[2]), "=r"(r[3]) : "r"(addr));
}
static __device__ __forceinline__ void mma_fp16(float* d, const uint32_t* a,
                                                uint32_t b0, uint32_t b1) {
    asm volatile(
        "mma.sync.aligned.m16n8k16.row.col.f32.f16.f16.f32 "
        "{%0,%1,%2,%3}, {%4,%5,%6,%7}, {%8,%9}, {%0,%1,%2,%3};"
        : "+f"(d[0]), "+f"(d[1]), "+f"(d[2]), "+f"(d[3])
        : "r"(a[0]), "r"(a[1]), "r"(a[2]), "r"(a[3]), "r"(b0), "r"(b1));
}
static __device__ __forceinline__ void cpasync16(uint32_t sa, const void* g) {
    asm volatile("cp.async.cg.shared.global [%0], [%1], 16;"
                 :: "r"(sa), "l"(g) : "memory");
}
static __device__ __forceinline__ void cp_commit() {
    asm volatile("cp.async.commit_group;" ::: "memory");
}
static __device__ __forceinline__ void cp_wait1() {
    asm volatile("cp.async.wait_group 1;" ::: "memory");
}
static __device__ __forceinline__ uint32_t pack_h2(float x, float y) {
    __half2 h = __floats2half2_rn(x, y);
    return *(uint32_t*)&h;
}

// ---------------------------------------------------------------------------
// Pipelined GEMM: D[128x128] = A[m0..,K] * B[n0..,K]^T (+ epilogue)
// 2-stage cp.async, K-chunk 64. Row stride 72 fp16 (144 B) — granule
// (9r+c)%8 distinct over 8 rows -> conflict-free ldmatrix.
// Stage: A@0 (18432 B) | B@18432 (18432 B); 2 stages = 73728 B -> 2 CTA/SM.
// MODE 0: fp32 +bias [qkv]; 1: relu+bias -> fp16 [ffn1]; 2: resid += [wo,ffn2]
// ---------------------------------------------------------------------------
#define RW 72
#define ARRB 18432
#define STGB (2 * ARRB)

template <int MODE>
static __device__ __forceinline__ void gemm_body(
    const __half* __restrict__ A, const __half* __restrict__ B,
    const float* __restrict__ bias, float* __restrict__ outF,
    __half* __restrict__ outH, float* __restrict__ resid,
    int K, int out_ld) {
    extern __shared__ __half sm[];

    const int tid = threadIdx.x;
    const int wid = tid >> 5;
    const int lane = tid & 31;
    const int wm = wid >> 2;       // 0..1 (64 rows)
    const int wn = wid & 3;        // 0..3 (32 cols)
    const int n0 = blockIdx.x * 128;
    const int m0 = blockIdx.y * 128;

    const __half* __restrict__ gA = A + (size_t)m0 * K;
    const __half* __restrict__ gB = B + (size_t)n0 * K;
    const uint32_t smBase = smem_u32(sm);

    float acc[4][4][4];
#pragma unroll
    for (int mt = 0; mt < 4; ++mt)
#pragma unroll
        for (int nt = 0; nt < 4; ++nt)
#pragma unroll
            for (int e = 0; e < 4; ++e) acc[mt][nt][e] = 0.f;

    const int nst = K >> 6;

    auto load_stage = [&](int s) {
        const uint32_t sb = smBase + (uint32_t)((s & 1) * STGB);
        const int kc = s * 64;
#pragma unroll
        for (int i = 0; i < 8; ++i) {
            const int idx = tid + i * 256;       // 0..2047
            const int a2 = idx >> 10;            // 0=A, 1=B
            const int r = (idx >> 3) & 127;
            const int c = idx & 7;
            const uint32_t sa = sb + (uint32_t)(a2 * ARRB + r * 144 + c * 16);
            const __half* g = (a2 == 0 ? gA : gB);
            cpasync16(sa, g + (size_t)r * K + kc + c * 8);
        }
        cp_commit();
    };

    load_stage(0);
    if (nst > 1) load_stage(1); else cp_commit();

    const uint32_t aOff = (uint32_t)((wm * 64 + (lane & 15)) * 144 + ((lane >> 4) << 4));
    const uint32_t bOff = (uint32_t)((wn * 32 + (lane & 15)) * 144 + ((lane >> 4) << 4));

    for (int s = 0; s < nst; ++s) {
        cp_wait1();
        __syncthreads();
        const uint32_t sb = smBase + (uint32_t)((s & 1) * STGB);
        const uint32_t aB = sb + aOff;
        const uint32_t bB = sb + ARRB + bOff;
#pragma unroll
        for (int st = 0; st < 4; ++st) {                 // 4 x k16
            const uint32_t koff = (uint32_t)(st * 32);   // 16 fp16 = 32 B
            uint32_t bfr[2][4];
            ldm4(bfr[0], bB + koff);
            ldm4(bfr[1], bB + koff + 16 * 144);
            uint32_t afr[4][4];
            ldm4(afr[0], aB + koff);
            ldm4(afr[1], aB + koff + 16 * 144);
            ldm4(afr[2], aB + koff + 32 * 144);
            ldm4(afr[3], aB + koff + 48 * 144);
            // 16 independent accumulators per k16 step
#pragma unroll
            for (int mt = 0; mt < 4; ++mt)
#pragma unroll
                for (int nt = 0; nt < 4; ++nt) {
                    const int np = nt >> 1, sel = nt & 1;
                    mma_fp16(acc[mt][nt], afr[mt],
                             bfr[np][sel], bfr[np][sel + 2]);
                }
        }
        __syncthreads();
        if (s + 2 < nst) load_stage(s + 2);
        else cp_commit();
    }

    const int r0 = lane >> 2;
    const int c0 = (lane & 3) * 2;
#pragma unroll
    for (int mt = 0; mt < 4; ++mt) {
#pragma unroll
        for (int nt = 0; nt < 4; ++nt) {
            const int gc = n0 + wn * 32 + nt * 8 + c0;
            const float bx = bias[gc], by = bias[gc + 1];
#pragma unroll
            for (int half = 0; half < 2; ++half) {
                const int gr = m0 + wm * 64 + mt * 16 + r0 + half * 8;
                float vx = acc[mt][nt][2 * half] + bx;
                float vy = acc[mt][nt][2 * half + 1] + by;
                const size_t ro = (size_t)gr * out_ld + gc;
                if (MODE == 0) {
                    *(float2*)(outF + ro) = make_float2(vx, vy);
                } else if (MODE == 2) {
                    float2 xv = *(float2*)(resid + ro);
                    xv.x += vx; xv.y += vy;
                    *(float2*)(resid + ro) = xv;
                } else {
                    vx = fmaxf(vx, 0.f); vy = fmaxf(vy, 0.f);
                    *(uint32_t*)(outH + ro) = pack_h2(vx, vy);
                }
            }
        }
    }
}

__global__ void __launch_bounds__(256, 2)
k_gemm_qkv(const float* __restrict__ bias) {
    gemm_body<0>(g_h, g_Bqkv, bias, g_qkv, nullptr, nullptr, 256, 768);
}
__global__ void __launch_bounds__(256, 2)
k_gemm_wo(const float* __restrict__ bias, float* __restrict__ x) {
    gemm_body<2>(g_o, g_Bo, bias, nullptr, nullptr, x, 256, 256);
}
__global__ void __launch_bounds__(256, 2)
k_gemm_ffn1(const float* __restrict__ bias) {
    gemm_body<1>(g_h, g_B1, bias, nullptr, g_u, nullptr, 256, 1024);
}
__global__ void __launch_bounds__(256, 2)
k_gemm_ffn2(const float* __restrict__ bias, float* __restrict__ x) {
    gemm_body<2>(g_u, g_B2, bias, nullptr, nullptr, x, 1024, 256);
}

// ---------------- LayerNorm: x -> fp16 ---------------------------------------
__global__ void __launch_bounds__(256)
k_ln(const float* __restrict__ x, const float* __restrict__ g,
     const float* __restrict__ bta) {
    const int row = blockIdx.x * 8 + (threadIdx.x >> 5);
    const int lane = threadIdx.x & 31;
    const float* rp = x + (size_t)row * 256 + lane * 8;
    const float4 a = *(const float4*)rp;
    const float4 b4 = *(const float4*)(rp + 4);
    float vals[8] = {a.x, a.y, a.z, a.w, b4.x, b4.y, b4.z, b4.w};
    float s = 0.f, s2 = 0.f;
#pragma unroll
    for (int j = 0; j < 8; ++j) { s += vals[j]; s2 = fmaf(vals[j], vals[j], s2); }
#pragma unroll
    for (int off = 16; off; off >>= 1) {
        s += __shfl_xor_sync(0xffffffffu, s, off);
        s2 += __shfl_xor_sync(0xffffffffu, s2, off);
    }
    const float mean = s * 0.00390625f;
    const float var = s2 * 0.00390625f - mean * mean;
    const float rstd = rsqrtf(var + 1e-5f);
    uint32_t ph[4];
#pragma unroll
    for (int j = 0; j < 4; ++j) {
        const int c0 = lane * 8 + 2 * j;
        float v0 = (vals[2 * j] - mean) * rstd * g[c0] + bta[c0];
        float v1 = (vals[2 * j + 1] - mean) * rstd * g[c0 + 1] + bta[c0 + 1];
        ph[j] = pack_h2(v0, v1);
    }
    const size_t o = (size_t)row * 256 + lane * 8;
    *(uint4*)(g_h + o) = make_uint4(ph[0], ph[1], ph[2], ph[3]);
}

// ---------------- Attention (fp32, banded |i-j|<=1) --------------------------
__global__ void __launch_bounds__(256, 2)
k_attn() {
    extern __shared__ float smf[];  // [32][776]
    const int b = blockIdx.x;
    const int tid = threadIdx.x;
    const int wid = tid >> 5;
    const int lane = tid & 31;
    const float* gq = g_qkv + (size_t)b * 24576;
    for (int r = wid; r < 32; r += 8)
#pragma unroll
        for (int j = 0; j < 24; ++j)
            smf[r * 776 + j * 32 + lane] = gq[r * 768 + j * 32 + lane];
    __syncthreads();

    const int h = wid;
    float kreg[32];
#pragma unroll
    for (int d = 0; d < 32; ++d)
        kreg[d] = smf[lane * 776 + 256 + h * 32 + d];
    const float SC = 0.17677669529663689f;
    for (int i = 0; i < 32; ++i) {
        const float* qrow = smf + i * 776 + h * 32;
        float s = 0.f;
#pragma unroll
        for (int d = 0; d < 32; ++d) s = fmaf(qrow[d], kreg[d], s);
        s *= SC;
        int dj = lane - i;
        if (dj < 0) dj = -dj;
        if (dj > 1) s -= 1e9f;
        float m = s;
#pragma unroll
        for (int off = 16; off; off >>= 1)
            m = fmaxf(m, __shfl_xor_sync(0xffffffffu, m, off));
        const float e = expf(s - m);
        float sum = e;
#pragma unroll
        for (int off = 16; off; off >>= 1)
            sum += __shfl_xor_sync(0xffffffffu, sum, off);
        const float w = e / sum;
        float o = 0.f;
        const int j0 = (i > 0) ? i - 1 : 0;
        const int j1 = (i < 31) ? i + 1 : 31;
        for (int j = j0; j <= j1; ++j) {
            const float wj = __shfl_sync(0xffffffffu, w, j);
            o = fmaf(wj, smf[j * 776 + 512 + h * 32 + lane], o);
        }
        g_o[(size_t)(b * 32 + i) * 256 + h * 32 + lane] = __float2half_rn(o);
    }
}

// ---------------- merged weight prep ----------------------------------------
__global__ void k_split_all(const float* __restrict__ wqkv,
                            const float* __restrict__ wo,
                            const float* __restrict__ w1,
                            const float* __restrict__ w2) {
    int i = blockIdx.x * 256 + threadIdx.x;
    if (i < 196608) {
        g_Bqkv[i] = __float2half_rn(wqkv[i]);
    } else if (i < 262144) {
        int j = i - 196608;
        g_Bo[j] = __float2half_rn(wo[j]);
    } else if (i < 524288) {
        int j = i - 262144;
        int f = j >> 8, k = j & 255;
        g_B1[j] = __float2half_rn(w1[k * 1024 + f]);
    } else if (i < 786432) {
        int j = i - 524288;
        int c = j >> 10, k = j & 1023;
        g_B2[j] = __float2half_rn(w2[k * 256 + c]);
    }
}

// ---------------- Tokenizer (fp32, proven) -----------------------------------
__global__ void __launch_bounds__(256)
bt_tokenize(const float* __restrict__ obs, const float* __restrict__ embW,
            const float* __restrict__ embB, const float* __restrict__ pos,
            float* __restrict__ out) {
    __shared__ float obs_s[32 * 128];
    const int n = blockIdx.x;
    const int b0 = blockIdx.y * 32;
    const int tid = threadIdx.x;
    const float* src = obs + b0 * 128;
    for (int i = tid; i < 4096; i += 256) obs_s[i] = src[i];
    __syncthreads();
    const int e = tid;
    float acc[32];
#pragma unroll
    for (int bb = 0; bb < 32; ++bb) acc[bb] = 0.f;
    const float* wb = embW + n * 32768 + e;
    for (int d0 = 0; d0 < 128; d0 += 16) {
        float w[16];
#pragma unroll
        for (int dd = 0; dd < 16; ++dd) w[dd] = wb[(d0 + dd) * 256];
#pragma unroll
        for (int bb = 0; bb < 32; ++bb) {
            const float4* orow = (const float4*)(obs_s + bb * 128 + d0);
            float4 o0 = orow[0], o1 = orow[1], o2 = orow[2], o3 = orow[3];
            float a = acc[bb];
            a = fmaf(o0.x, w[0], a);  a = fmaf(o0.y, w[1], a);
            a = fmaf(o0.z, w[2], a);  a = fmaf(o0.w, w[3], a);
            a = fmaf(o1.x, w[4], a);  a = fmaf(o1.y, w[5], a);
            a = fmaf(o1.z, w[6], a);  a = fmaf(o1.w, w[7], a);
            a = fmaf(o2.x, w[8], a);  a = fmaf(o2.y, w[9], a);
            a = fmaf(o2.z, w[10], a); a = fmaf(o2.w, w[11], a);
            a = fmaf(o3.x, w[12], a); a = fmaf(o3.y, w[13], a);
            a = fmaf(o3.z, w[14], a); a = fmaf(o3.w, w[15], a);
            acc[bb] = a;
        }
    }
    const float add = embB[n * 256 + e] + pos[n * 256 + e];
#pragma unroll
    for (int bb = 0; bb < 32; ++bb)
        out[(b0 + bb) * 8192 + n * 256 + e] = acc[bb] + add;
}

extern "C" void kernel_launch(void* const* d_in, const int* in_sizes, int n_in,
                              void* d_out, int out_size) {
    (void)in_sizes; (void)n_in; (void)out_size;
    const float* obs  = (const float*)d_in[0];
    const float* embW = (const float*)d_in[1];
    const float* embB = (const float*)d_in[2];
    const float* pos  = (const float*)d_in[3];
    const float* Wqkv = (const float*)d_in[4];
    const float* bqkv = (const float*)d_in[5];
    const float* Wo   = (const float*)d_in[6];
    const float* bo   = (const float*)d_in[7];
    const float* ln1g = (const float*)d_in[8];
    const float* ln1b = (const float*)d_in[9];
    const float* ln2g = (const float*)d_in[10];
    const float* ln2b = (const float*)d_in[11];
    const float* W1   = (const float*)d_in[12];
    const float* b1   = (const float*)d_in[13];
    const float* W2   = (const float*)d_in[14];
    const float* b2   = (const float*)d_in[15];
    float* x = (float*)d_out;

    const int GSMEM = 2 * STGB;       // 73728 B
    const int ASMEM = 32 * 776 * 4;   // 99328 B
    cudaFuncSetAttribute(k_gemm_qkv,  cudaFuncAttributeMaxDynamicSharedMemorySize, GSMEM);
    cudaFuncSetAttribute(k_gemm_wo,   cudaFuncAttributeMaxDynamicSharedMemorySize, GSMEM);
    cudaFuncSetAttribute(k_gemm_ffn1, cudaFuncAttributeMaxDynamicSharedMemorySize, GSMEM);
    cudaFuncSetAttribute(k_gemm_ffn2, cudaFuncAttributeMaxDynamicSharedMemorySize, GSMEM);
    cudaFuncSetAttribute(k_attn,      cudaFuncAttributeMaxDynamicSharedMemorySize, ASMEM);

    k_split_all<<<3072, 256>>>(Wqkv, Wo, W1, W2);
    bt_tokenize<<<dim3(32, 128), 256>>>(obs, embW, embB, pos, x);

    for (int l = 0; l < 6; ++l) {
        k_ln<<<16384, 256>>>(x, ln1g, ln1b);
        k_gemm_qkv<<<dim3(6, 1024), 256, GSMEM>>>(bqkv);
        k_attn<<<4096, 256, ASMEM>>>();
        k_gemm_wo<<<dim3(2, 1024), 256, GSMEM>>>(bo, x);
        k_ln<<<16384, 256>>>(x, ln2g, ln2b);
        k_gemm_ffn1<<<dim3(8, 1024), 256, GSMEM>>>(b1);
        k_gemm_ffn2<<<dim3(2, 1024), 256, GSMEM>>>(b2, x);
    }
}